// round 13
// baseline (speedup 1.0000x reference)
#include <cuda_runtime.h>
#include <cuda_fp16.h>
#include <math.h>
#include <stdint.h>

#define B_   256
#define T_   256
#define C_   512
#define H_   64
#define BT_  (B_ * T_)

// projected q (pre-scaled by C^-0.5), k, v as fp16
__device__ __half g_q16[BT_ * H_];
__device__ __half g_k16[BT_ * H_];
__device__ __half g_v16[BT_ * H_];

// W in B-operand layout [w][n=64][k=512], fp16
__device__ __half g_w16[3 * H_ * C_];

// ---------------------------------------------------------------------------
// helpers
// ---------------------------------------------------------------------------
__device__ __forceinline__ uint32_t smem_u32(const void* p) {
    uint32_t a;
    asm("{ .reg .u64 t; cvta.to.shared.u64 t, %1; cvt.u32.u64 %0, t; }"
        : "=r"(a) : "l"(p));
    return a;
}

__device__ __forceinline__ void ldsm_x4(uint32_t& r0, uint32_t& r1,
                                        uint32_t& r2, uint32_t& r3,
                                        uint32_t addr) {
    asm volatile("ldmatrix.sync.aligned.m8n8.x4.shared.b16 {%0,%1,%2,%3}, [%4];"
                 : "=r"(r0), "=r"(r1), "=r"(r2), "=r"(r3) : "r"(addr));
}

__device__ __forceinline__ void ldsm_x4_t(uint32_t& r0, uint32_t& r1,
                                          uint32_t& r2, uint32_t& r3,
                                          uint32_t addr) {
    asm volatile("ldmatrix.sync.aligned.m8n8.x4.trans.shared.b16 {%0,%1,%2,%3}, [%4];"
                 : "=r"(r0), "=r"(r1), "=r"(r2), "=r"(r3) : "r"(addr));
}

__device__ __forceinline__ void mma_f16(float* c, const uint32_t* a,
                                        const uint32_t* b) {
    asm volatile(
        "mma.sync.aligned.m16n8k16.row.col.f32.f16.f16.f32 "
        "{%0,%1,%2,%3}, {%4,%5,%6,%7}, {%8,%9}, {%0,%1,%2,%3};"
        : "+f"(c[0]), "+f"(c[1]), "+f"(c[2]), "+f"(c[3])
        : "r"(a[0]), "r"(a[1]), "r"(a[2]), "r"(a[3]),
          "r"(b[0]), "r"(b[1]));
}

__device__ __forceinline__ uint32_t pack_h2(float lo, float hi) {
    __half2 t = __floats2half2_rn(lo, hi);
    return *(uint32_t*)&t;
}

__device__ __forceinline__ void cp_async16(uint32_t smem_addr, const void* gptr) {
    asm volatile("cp.async.cg.shared.global [%0], [%1], 16;"
                 :: "r"(smem_addr), "l"(gptr));
}
#define CP_COMMIT()  asm volatile("cp.async.commit_group;")
#define CP_WAIT(N)   asm volatile("cp.async.wait_group %0;" :: "n"(N))

#define RS2 144   // smem row stride in bytes (72 halves)

// ---------------------------------------------------------------------------
// Kernel 0: W -> fp16 in [w][h][c] layout (smem tile transpose, coalesced)
// ---------------------------------------------------------------------------
__global__ void wconv(const float* __restrict__ Wq,
                      const float* __restrict__ Wk,
                      const float* __restrict__ Wv)
{
    __shared__ float tile[32][33];
    const int w  = blockIdx.z;
    const int c0 = blockIdx.x * 32;
    const int h0 = blockIdx.y * 32;
    const float* W = (w == 0) ? Wq : (w == 1) ? Wk : Wv;

    const int tx = threadIdx.x & 31;
    const int ty = threadIdx.x >> 5;

#pragma unroll
    for (int i = 0; i < 4; i++) {
        int r = ty + i * 8;
        tile[r][tx] = W[(size_t)(c0 + r) * H_ + h0 + tx];
    }
    __syncthreads();
#pragma unroll
    for (int i = 0; i < 4; i++) {
        int hh = ty + i * 8;
        g_w16[((size_t)w * H_ + h0 + hh) * C_ + c0 + tx] =
            __float2half(tile[tx][hh]);
    }
}

// ---------------------------------------------------------------------------
// Kernel 1: pipelined fused QKV projection, fp16 (R8 pipeline, merged CTAs).
// CTA: 128 rows x 192 cols, 512 threads, 16 warps (4M x 4N), warp tile 32x48.
// Same per-SMSP warp count as R8 (4), half the per-CTA W traffic.
// K = 512 in 8 chunks of 64. B double-buffered via cp.async; x prefetched
// into registers one chunk ahead. Two barriers per chunk (R8 structure).
// smem: A 0 (18432), B0 18432 (27648), B1 46080 (27648); total 73728
// ---------------------------------------------------------------------------
#define QK_A  0
#define QK_B0 18432
#define QK_B1 46080
#define QK_SMEM 73728

__global__ __launch_bounds__(512, 1) void qkv_gemm_pipe(
    const float* __restrict__ x)
{
    extern __shared__ char sm[];
    const uint32_t smb = smem_u32(sm);

    const int tid  = threadIdx.x;
    const int wid  = tid >> 5;
    const int lane = tid & 31;
    const int row0 = blockIdx.x * 128;

    const int wm = wid & 3;           // 4 M groups of 32
    const int wn = wid >> 2;          // 4 N groups of 48
    const int m0 = wm * 32;
    const int n0 = wn * 48;

    float c[2][6][4];
#pragma unroll
    for (int mt = 0; mt < 2; mt++)
#pragma unroll
        for (int nt = 0; nt < 6; nt++)
#pragma unroll
            for (int i = 0; i < 4; i++) c[mt][nt][i] = 0.f;

    const uint32_t a_row_off = (uint32_t)(m0 + (lane & 15)) * RS2
                             + (uint32_t)(lane >> 4) * 16;
    const uint32_t b_row_off = (uint32_t)(n0 + ((lane >> 4) & 1) * 8 + (lane & 7)) * RS2
                             + (uint32_t)((lane >> 3) & 1) * 16;

    const float4* x4 = (const float4*)x;

    // prologue: B chunk 0 via cp.async, x chunk 0 into regs
    {
#pragma unroll
        for (int it = 0; it < 3; it++) {
            int idx = tid + it * 512;          // 0..1535
            int n = idx >> 3, part = idx & 7;
            size_t gs = ((size_t)n * C_) * 2 + (size_t)part * 16;
            uint32_t off = (uint32_t)n * RS2 + (uint32_t)part * 16;
            cp_async16(smb + QK_B0 + off, (const char*)g_w16 + gs);
        }
        CP_COMMIT();
    }

    float4 xv[4];
#pragma unroll
    for (int it = 0; it < 4; it++) {
        int idx = tid + it * 512;               // 0..2047
        int r = idx >> 4, c4 = idx & 15;
        xv[it] = x4[(size_t)(row0 + r) * 128 + c4];
    }

    for (int ch = 0; ch < 8; ch++) {
        // convert x regs -> A fp16 smem
#pragma unroll
        for (int it = 0; it < 4; it++) {
            int idx = tid + it * 512;
            int r = idx >> 4, c4 = idx & 15;
            float4 v = xv[it];
            uint32_t off = (uint32_t)r * RS2 + (uint32_t)c4 * 8;
            *(uint2*)(sm + QK_A + off) =
                make_uint2(pack_h2(v.x, v.y), pack_h2(v.z, v.w));
        }

        // prefetch chunk ch+1
        if (ch < 7) {
            const int c1 = (ch + 1) * 64;
#pragma unroll
            for (int it = 0; it < 4; it++) {
                int idx = tid + it * 512;
                int r = idx >> 4, c4 = idx & 15;
                xv[it] = x4[(size_t)(row0 + r) * 128 + (c1 >> 2) + c4];
            }
            const uint32_t bb = ((ch + 1) & 1) ? QK_B1 : QK_B0;
#pragma unroll
            for (int it = 0; it < 3; it++) {
                int idx = tid + it * 512;
                int n = idx >> 3, part = idx & 7;
                size_t gs = ((size_t)n * C_ + c1) * 2 + (size_t)part * 16;
                uint32_t off = (uint32_t)n * RS2 + (uint32_t)part * 16;
                cp_async16(smb + bb + off, (const char*)g_w16 + gs);
            }
            CP_COMMIT();
            CP_WAIT(1);
        } else {
            CP_WAIT(0);
        }
        __syncthreads();

        const uint32_t bbuf = (ch & 1) ? QK_B1 : QK_B0;
#pragma unroll
        for (int ks = 0; ks < 4; ks++) {
            uint32_t a[2][4];
#pragma unroll
            for (int mt = 0; mt < 2; mt++) {
                uint32_t off = a_row_off + (uint32_t)mt * 16 * RS2 + (uint32_t)ks * 32;
                ldsm_x4(a[mt][0], a[mt][1], a[mt][2], a[mt][3], smb + QK_A + off);
            }
            uint32_t bfr[6][2];
#pragma unroll
            for (int np = 0; np < 3; np++) {
                uint32_t off = b_row_off + (uint32_t)np * 16 * RS2 + (uint32_t)ks * 32;
                ldsm_x4(bfr[np*2][0], bfr[np*2][1], bfr[np*2+1][0], bfr[np*2+1][1],
                        smb + bbuf + off);
            }
#pragma unroll
            for (int mt = 0; mt < 2; mt++)
#pragma unroll
                for (int nt = 0; nt < 6; nt++)
                    mma_f16(c[mt][nt], a[mt], bfr[nt]);
        }
        __syncthreads();
    }

    // epilogue: fp16 writes; q pre-scaled by C^-0.5
    const float SCALE = 0.04419417382415922f;
    const int g  = lane >> 2;
    const int tg = lane & 3;
#pragma unroll
    for (int nt = 0; nt < 6; nt++) {
        int col0 = n0 + nt * 8;
        int w = col0 >> 6;
        int h = (col0 & 63) + tg * 2;
        float mul = (w == 0) ? SCALE : 1.0f;
        __half* op = (w == 0) ? g_q16 : (w == 1) ? g_k16 : g_v16;
#pragma unroll
        for (int mt = 0; mt < 2; mt++)
#pragma unroll
            for (int rr = 0; rr < 2; rr++) {
                int row = row0 + m0 + mt * 16 + g + rr * 8;
                size_t o = (size_t)row * H_ + h;
                *(uint32_t*)(op + o) = pack_h2(c[mt][nt][rr * 2 + 0] * mul,
                                               c[mt][nt][rr * 2 + 1] * mul);
            }
    }
}

// ---------------------------------------------------------------------------
// Kernel 2: fp16 tensor-core causal flash attention (R8/R10, unchanged).
// ---------------------------------------------------------------------------
#define AT_Q  0
#define AT_ST0 18432
#define AT_STAGE 18432
#define AT_K 0
#define AT_V 9216
#define A_SMEM 55296

__global__ __launch_bounds__(256, 2) void attn_mma(float* __restrict__ out)
{
    extern __shared__ char sm[];
    const uint32_t smb = smem_u32(sm);

    const int b    = blockIdx.x;
    const int qt   = 1 - blockIdx.y;           // heavy tile first
    const int tid  = threadIdx.x;
    const int w    = tid >> 5;
    const int lane = tid & 31;
    const int g    = lane >> 2;
    const int tg   = lane & 3;

    const int rowbase = qt * 128 + w * 16;
    const int nkt = qt * 2 + 2;

    // Q tile (128 rows) + prologue K/V stage 0
    {
        const size_t base = ((size_t)b * T_ + qt * 128) * H_;   // halves
        for (int idx = tid; idx < 1024; idx += 256) {
            int r = idx >> 3, part = idx & 7;
            size_t gs = (base + (size_t)r * H_ + part * 8) * 2;
            uint32_t off = (uint32_t)r * RS2 + part * 16;
            *(uint4*)(sm + AT_Q + off) = *(const uint4*)((const char*)g_q16 + gs);
        }
        const size_t kbase = ((size_t)b * T_) * H_;
        const uint32_t stg = smb + AT_ST0;
        for (int idx = tid; idx < 512; idx += 256) {
            int r = idx >> 3, part = idx & 7;
            size_t gs = (kbase + (size_t)r * H_ + part * 8) * 2;
            uint32_t off = (uint32_t)r * RS2 + part * 16;
            cp_async16(stg + AT_K + off, (const char*)g_k16 + gs);
            cp_async16(stg + AT_V + off, (const char*)g_v16 + gs);
        }
        CP_COMMIT();
    }
    __syncthreads();

    // preload Q A-frags
    uint32_t qa[4][4];
    {
        uint32_t a_row_off = (uint32_t)(w * 16 + (lane & 15)) * RS2
                           + (uint32_t)(lane >> 4) * 16;
#pragma unroll
        for (int ks = 0; ks < 4; ks++)
            ldsm_x4(qa[ks][0], qa[ks][1], qa[ks][2], qa[ks][3],
                    smb + AT_Q + a_row_off + ks * 32);
    }

    float o[8][4];
#pragma unroll
    for (int nt = 0; nt < 8; nt++)
#pragma unroll
        for (int i = 0; i < 4; i++) o[nt][i] = 0.f;
    float m0r = -INFINITY, m1r = -INFINITY;
    float l0r = 0.f, l1r = 0.f;

    const uint32_t kb_off = (uint32_t)(((lane >> 4) & 1) * 8 + (lane & 7)) * RS2
                          + (uint32_t)((lane >> 3) & 1) * 16;
    const uint32_t vb_off = (uint32_t)(((lane >> 3) & 1) * 8 + (lane & 7)) * RS2
                          + (uint32_t)((lane >> 4) & 1) * 16;

    for (int kt = 0; kt < nkt; kt++) {
        if (kt + 1 < nkt) {
            const size_t kbase = ((size_t)b * T_ + (kt + 1) * 64) * H_;
            const uint32_t stg = smb + AT_ST0 + ((kt + 1) & 1) * AT_STAGE;
            for (int idx = tid; idx < 512; idx += 256) {
                int r = idx >> 3, part = idx & 7;
                size_t gs = (kbase + (size_t)r * H_ + part * 8) * 2;
                uint32_t off = (uint32_t)r * RS2 + part * 16;
                cp_async16(stg + AT_K + off, (const char*)g_k16 + gs);
                cp_async16(stg + AT_V + off, (const char*)g_v16 + gs);
            }
            CP_COMMIT();
            CP_WAIT(1);
        } else {
            CP_WAIT(0);
        }
        __syncthreads();

        const int kcol0 = kt * 64;
        if (kcol0 <= rowbase + 15) {
            const uint32_t stg = smb + AT_ST0 + (kt & 1) * AT_STAGE;

            // S = Q K^T
            float s[8][4];
#pragma unroll
            for (int nt = 0; nt < 8; nt++)
#pragma unroll
                for (int i = 0; i < 4; i++) s[nt][i] = 0.f;

#pragma unroll
            for (int ks = 0; ks < 4; ks++) {
                uint32_t bfr[8][2];
#pragma unroll
                for (int np = 0; np < 4; np++) {
                    uint32_t off = kb_off + (uint32_t)np * 16 * RS2 + (uint32_t)ks * 32;
                    ldsm_x4(bfr[np*2][0], bfr[np*2][1], bfr[np*2+1][0], bfr[np*2+1][1],
                            stg + AT_K + off);
                }
#pragma unroll
                for (int nt = 0; nt < 8; nt++)
                    mma_f16(s[nt], qa[ks], bfr[nt]);
            }

            // causal mask (diagonal region)
            if (kcol0 + 63 > rowbase) {
                const int r0g = rowbase + g;
#pragma unroll
                for (int nt = 0; nt < 8; nt++) {
                    int cg = kcol0 + nt * 8 + tg * 2;
                    if (cg > r0g)         s[nt][0] = -1e30f;
                    if (cg + 1 > r0g)     s[nt][1] = -1e30f;
                    if (cg > r0g + 8)     s[nt][2] = -1e30f;
                    if (cg + 1 > r0g + 8) s[nt][3] = -1e30f;
                }
            }

            // online softmax
            float mt0 = -INFINITY, mt1 = -INFINITY;
#pragma unroll
            for (int nt = 0; nt < 8; nt++) {
                mt0 = fmaxf(mt0, fmaxf(s[nt][0], s[nt][1]));
                mt1 = fmaxf(mt1, fmaxf(s[nt][2], s[nt][3]));
            }
            mt0 = fmaxf(mt0, __shfl_xor_sync(0xffffffff, mt0, 1));
            mt0 = fmaxf(mt0, __shfl_xor_sync(0xffffffff, mt0, 2));
            mt1 = fmaxf(mt1, __shfl_xor_sync(0xffffffff, mt1, 1));
            mt1 = fmaxf(mt1, __shfl_xor_sync(0xffffffff, mt1, 2));

            float mn0 = fmaxf(m0r, mt0);
            float mn1 = fmaxf(m1r, mt1);
            float cr0 = __expf(m0r - mn0);
            float cr1 = __expf(m1r - mn1);
            m0r = mn0; m1r = mn1;

            float ls0 = 0.f, ls1 = 0.f;
#pragma unroll
            for (int nt = 0; nt < 8; nt++) {
                s[nt][0] = __expf(s[nt][0] - mn0);
                s[nt][1] = __expf(s[nt][1] - mn0);
                s[nt][2] = __expf(s[nt][2] - mn1);
                s[nt][3] = __expf(s[nt][3] - mn1);
                ls0 += s[nt][0] + s[nt][1];
                ls1 += s[nt][2] + s[nt][3];
            }
            l0r = l0r * cr0 + ls0;
            l1r = l1r * cr1 + ls1;

#pragma unroll
            for (int nt = 0; nt < 8; nt++) {
                o[nt][0] *= cr0; o[nt][1] *= cr0;
                o[nt][2] *= cr1; o[nt][3] *= cr1;
            }

            // repack P -> fp16 A-frags
            uint32_t pa[4][4];
#pragma unroll
            for (int j = 0; j < 4; j++) {
                pa[j][0] = pack_h2(s[2*j][0],   s[2*j][1]);
                pa[j][1] = pack_h2(s[2*j][2],   s[2*j][3]);
                pa[j][2] = pack_h2(s[2*j+1][0], s[2*j+1][1]);
                pa[j][3] = pack_h2(s[2*j+1][2], s[2*j+1][3]);
            }

            // O += P V
#pragma unroll
            for (int ks = 0; ks < 4; ks++) {
                uint32_t vb[8][2];
#pragma unroll
                for (int nt2 = 0; nt2 < 4; nt2++) {
                    uint32_t off = vb_off + (uint32_t)(ks * 16) * RS2 + (uint32_t)nt2 * 32;
                    ldsm_x4_t(vb[nt2*2][0], vb[nt2*2][1], vb[nt2*2+1][0], vb[nt2*2+1][1],
                              stg + AT_V + off);
                }
#pragma unroll
                for (int nt = 0; nt < 8; nt++)
                    mma_f16(o[nt], pa[ks], vb[nt]);
            }
        }
        __syncthreads();
    }

    // finalize
    l0r += __shfl_xor_sync(0xffffffff, l0r, 1);
    l0r += __shfl_xor_sync(0xffffffff, l0r, 2);
    l1r += __shfl_xor_sync(0xffffffff, l1r, 1);
    l1r += __shfl_xor_sync(0xffffffff, l1r, 2);
    float inv0 = 1.f / l0r;
    float inv1 = 1.f / l1r;

    const int q0 = rowbase + g;
#pragma unroll
    for (int nt = 0; nt < 8; nt++) {
        int h = nt * 8 + tg * 2;
        *(float2*)&out[((size_t)b * T_ + q0) * H_ + h] =
            make_float2(o[nt][0] * inv0, o[nt][1] * inv0);
        *(float2*)&out[((size_t)b * T_ + q0 + 8) * H_ + h] =
            make_float2(o[nt][2] * inv1, o[nt][3] * inv1);
    }
}

// ---------------------------------------------------------------------------
extern "C" void kernel_launch(void* const* d_in, const int* in_sizes, int n_in,
                              void* d_out, int out_size)
{
    const float* x  = (const float*)d_in[0];
    const float* Wk = (const float*)d_in[1];
    const float* Wq = (const float*)d_in[2];
    const float* Wv = (const float*)d_in[3];
    float* out = (float*)d_out;

    cudaFuncSetAttribute(qkv_gemm_pipe,
                         cudaFuncAttributeMaxDynamicSharedMemorySize, QK_SMEM);
    cudaFuncSetAttribute(attn_mma,
                         cudaFuncAttributeMaxDynamicSharedMemorySize, A_SMEM);

    dim3 gw(C_ / 32, H_ / 32, 3);
    wconv<<<gw, 256>>>(Wq, Wk, Wv);
    qkv_gemm_pipe<<<BT_ / 128, 512, QK_SMEM>>>(x);

    dim3 g2(B_, T_ / 128);
    attn_mma<<<g2, 256, A_SMEM>>>(out);
}

// round 14
// speedup vs baseline: 1.1656x; 1.1656x over previous
#include <cuda_runtime.h>
#include <cuda_fp16.h>
#include <math.h>
#include <stdint.h>

#define B_   256
#define T_   256
#define C_   512
#define H_   64
#define BT_  (B_ * T_)

// projected q (pre-scaled by C^-0.5), k, v as fp16
__device__ __half g_q16[BT_ * H_];
__device__ __half g_k16[BT_ * H_];
__device__ __half g_v16[BT_ * H_];

// W in B-operand layout [w][n=64][k=512], fp16
__device__ __half g_w16[3 * H_ * C_];

// ---------------------------------------------------------------------------
// helpers
// ---------------------------------------------------------------------------
__device__ __forceinline__ uint32_t smem_u32(const void* p) {
    uint32_t a;
    asm("{ .reg .u64 t; cvta.to.shared.u64 t, %1; cvt.u32.u64 %0, t; }"
        : "=r"(a) : "l"(p));
    return a;
}

__device__ __forceinline__ void ldsm_x4(uint32_t& r0, uint32_t& r1,
                                        uint32_t& r2, uint32_t& r3,
                                        uint32_t addr) {
    asm volatile("ldmatrix.sync.aligned.m8n8.x4.shared.b16 {%0,%1,%2,%3}, [%4];"
                 : "=r"(r0), "=r"(r1), "=r"(r2), "=r"(r3) : "r"(addr));
}

__device__ __forceinline__ void ldsm_x4_t(uint32_t& r0, uint32_t& r1,
                                          uint32_t& r2, uint32_t& r3,
                                          uint32_t addr) {
    asm volatile("ldmatrix.sync.aligned.m8n8.x4.trans.shared.b16 {%0,%1,%2,%3}, [%4];"
                 : "=r"(r0), "=r"(r1), "=r"(r2), "=r"(r3) : "r"(addr));
}

__device__ __forceinline__ void mma_f16(float* c, const uint32_t* a,
                                        const uint32_t* b) {
    asm volatile(
        "mma.sync.aligned.m16n8k16.row.col.f32.f16.f16.f32 "
        "{%0,%1,%2,%3}, {%4,%5,%6,%7}, {%8,%9}, {%0,%1,%2,%3};"
        : "+f"(c[0]), "+f"(c[1]), "+f"(c[2]), "+f"(c[3])
        : "r"(a[0]), "r"(a[1]), "r"(a[2]), "r"(a[3]),
          "r"(b[0]), "r"(b[1]));
}

__device__ __forceinline__ uint32_t pack_h2(float lo, float hi) {
    __half2 t = __floats2half2_rn(lo, hi);
    return *(uint32_t*)&t;
}

__device__ __forceinline__ void cp_async16(uint32_t smem_addr, const void* gptr) {
    asm volatile("cp.async.cg.shared.global [%0], [%1], 16;"
                 :: "r"(smem_addr), "l"(gptr));
}
#define CP_COMMIT()  asm volatile("cp.async.commit_group;")
#define CP_WAIT(N)   asm volatile("cp.async.wait_group %0;" :: "n"(N))

#define RS2 144   // smem row stride in bytes (72 halves)

// ---------------------------------------------------------------------------
// Kernel 0: W -> fp16 in [w][h][c] layout (smem tile transpose, coalesced)
// ---------------------------------------------------------------------------
__global__ void wconv(const float* __restrict__ Wq,
                      const float* __restrict__ Wk,
                      const float* __restrict__ Wv)
{
    __shared__ float tile[32][33];
    const int w  = blockIdx.z;
    const int c0 = blockIdx.x * 32;
    const int h0 = blockIdx.y * 32;
    const float* W = (w == 0) ? Wq : (w == 1) ? Wk : Wv;

    const int tx = threadIdx.x & 31;
    const int ty = threadIdx.x >> 5;

#pragma unroll
    for (int i = 0; i < 4; i++) {
        int r = ty + i * 8;
        tile[r][tx] = W[(size_t)(c0 + r) * H_ + h0 + tx];
    }
    __syncthreads();
#pragma unroll
    for (int i = 0; i < 4; i++) {
        int hh = ty + i * 8;
        g_w16[((size_t)w * H_ + h0 + hh) * C_ + c0 + tx] =
            __float2half(tile[tx][hh]);
    }
}

// ---------------------------------------------------------------------------
// Kernel 1: pipelined fused QKV projection, single-term fp16 (R8 config —
// measured local optimum: 256 threads, 2 CTAs/SM, 32x48 warp tiles,
// B double-buffered cp.async, x register-prefetched one chunk ahead).
// smem: A 0 (9216), B0 9216 (27648), B1 36864 (27648); total 64512
// ---------------------------------------------------------------------------
#define QK_A  0
#define QK_B0 9216
#define QK_B1 36864
#define QK_SMEM 64512

__global__ __launch_bounds__(256, 2) void qkv_gemm_pipe(
    const float* __restrict__ x)
{
    extern __shared__ char sm[];
    const uint32_t smb = smem_u32(sm);

    const int tid  = threadIdx.x;
    const int wid  = tid >> 5;
    const int lane = tid & 31;
    const int row0 = blockIdx.x * 64;

    const int wm = wid & 1;
    const int wn = wid >> 1;          // 0..3
    const int m0 = wm * 32;
    const int n0 = wn * 48;

    float c[2][6][4];
#pragma unroll
    for (int mt = 0; mt < 2; mt++)
#pragma unroll
        for (int nt = 0; nt < 6; nt++)
#pragma unroll
            for (int i = 0; i < 4; i++) c[mt][nt][i] = 0.f;

    const uint32_t a_row_off = (uint32_t)(m0 + (lane & 15)) * RS2
                             + (uint32_t)(lane >> 4) * 16;
    const uint32_t b_row_off = (uint32_t)(n0 + ((lane >> 4) & 1) * 8 + (lane & 7)) * RS2
                             + (uint32_t)((lane >> 3) & 1) * 16;

    const float4* x4 = (const float4*)x;

    // prologue: B chunk 0 via cp.async, x chunk 0 into regs
    {
#pragma unroll
        for (int it = 0; it < 6; it++) {
            int idx = tid + it * 256;          // 0..1535
            int n = idx >> 3, part = idx & 7;
            size_t gs = ((size_t)n * C_) * 2 + (size_t)part * 16;
            uint32_t off = (uint32_t)n * RS2 + (uint32_t)part * 16;
            cp_async16(smb + QK_B0 + off, (const char*)g_w16 + gs);
        }
        CP_COMMIT();
    }

    float4 xv[4];
#pragma unroll
    for (int it = 0; it < 4; it++) {
        int idx = tid + it * 256;
        int r = idx >> 4, c4 = idx & 15;
        xv[it] = x4[(size_t)(row0 + r) * 128 + c4];
    }

    for (int ch = 0; ch < 8; ch++) {
        // convert x regs -> A fp16 smem
#pragma unroll
        for (int it = 0; it < 4; it++) {
            int idx = tid + it * 256;
            int r = idx >> 4, c4 = idx & 15;
            float4 v = xv[it];
            uint32_t off = (uint32_t)r * RS2 + (uint32_t)c4 * 8;
            *(uint2*)(sm + QK_A + off) =
                make_uint2(pack_h2(v.x, v.y), pack_h2(v.z, v.w));
        }

        // prefetch chunk ch+1
        if (ch < 7) {
            const int c1 = (ch + 1) * 64;
#pragma unroll
            for (int it = 0; it < 4; it++) {
                int idx = tid + it * 256;
                int r = idx >> 4, c4 = idx & 15;
                xv[it] = x4[(size_t)(row0 + r) * 128 + (c1 >> 2) + c4];
            }
            const uint32_t bb = ((ch + 1) & 1) ? QK_B1 : QK_B0;
#pragma unroll
            for (int it = 0; it < 6; it++) {
                int idx = tid + it * 256;
                int n = idx >> 3, part = idx & 7;
                size_t gs = ((size_t)n * C_ + c1) * 2 + (size_t)part * 16;
                uint32_t off = (uint32_t)n * RS2 + (uint32_t)part * 16;
                cp_async16(smb + bb + off, (const char*)g_w16 + gs);
            }
            CP_COMMIT();
            CP_WAIT(1);
        } else {
            CP_WAIT(0);
        }
        __syncthreads();

        const uint32_t bbuf = (ch & 1) ? QK_B1 : QK_B0;
#pragma unroll
        for (int ks = 0; ks < 4; ks++) {
            uint32_t a[2][4];
#pragma unroll
            for (int mt = 0; mt < 2; mt++) {
                uint32_t off = a_row_off + (uint32_t)mt * 16 * RS2 + (uint32_t)ks * 32;
                ldsm_x4(a[mt][0], a[mt][1], a[mt][2], a[mt][3], smb + QK_A + off);
            }
            uint32_t bfr[6][2];
#pragma unroll
            for (int np = 0; np < 3; np++) {
                uint32_t off = b_row_off + (uint32_t)np * 16 * RS2 + (uint32_t)ks * 32;
                ldsm_x4(bfr[np*2][0], bfr[np*2][1], bfr[np*2+1][0], bfr[np*2+1][1],
                        smb + bbuf + off);
            }
#pragma unroll
            for (int mt = 0; mt < 2; mt++)
#pragma unroll
                for (int nt = 0; nt < 6; nt++)
                    mma_f16(c[mt][nt], a[mt], bfr[nt]);
        }
        __syncthreads();
    }

    // epilogue: fp16 writes; q pre-scaled by C^-0.5
    const float SCALE = 0.04419417382415922f;
    const int g  = lane >> 2;
    const int tg = lane & 3;
#pragma unroll
    for (int nt = 0; nt < 6; nt++) {
        int col0 = n0 + nt * 8;
        int w = col0 >> 6;
        int h = (col0 & 63) + tg * 2;
        float mul = (w == 0) ? SCALE : 1.0f;
        __half* op = (w == 0) ? g_q16 : (w == 1) ? g_k16 : g_v16;
#pragma unroll
        for (int mt = 0; mt < 2; mt++)
#pragma unroll
            for (int rr = 0; rr < 2; rr++) {
                int row = row0 + m0 + mt * 16 + g + rr * 8;
                size_t o = (size_t)row * H_ + h;
                *(uint32_t*)(op + o) = pack_h2(c[mt][nt][rr * 2 + 0] * mul,
                                               c[mt][nt][rr * 2 + 1] * mul);
            }
    }
}

// ---------------------------------------------------------------------------
// Kernel 2: fp16 tensor-core causal flash attention (R8 config — measured
// optimum: Q-tile 128, 256 threads, double-buffered K/V cp.async stages,
// per-warp causal skip, 2 CTAs/SM).
// smem: Q 0 (18432), stage0 @18432 (K 9216, V 9216), stage1 @36864. 55296 B.
// ---------------------------------------------------------------------------
#define AT_Q  0
#define AT_ST0 18432
#define AT_STAGE 18432
#define AT_K 0
#define AT_V 9216
#define A_SMEM 55296

__global__ __launch_bounds__(256, 2) void attn_mma(float* __restrict__ out)
{
    extern __shared__ char sm[];
    const uint32_t smb = smem_u32(sm);

    const int b    = blockIdx.x;
    const int qt   = 1 - blockIdx.y;           // heavy tile first
    const int tid  = threadIdx.x;
    const int w    = tid >> 5;
    const int lane = tid & 31;
    const int g    = lane >> 2;
    const int tg   = lane & 3;

    const int rowbase = qt * 128 + w * 16;
    const int nkt = qt * 2 + 2;

    // Q tile (128 rows) + prologue K/V stage 0
    {
        const size_t base = ((size_t)b * T_ + qt * 128) * H_;   // halves
        for (int idx = tid; idx < 1024; idx += 256) {
            int r = idx >> 3, part = idx & 7;
            size_t gs = (base + (size_t)r * H_ + part * 8) * 2;
            uint32_t off = (uint32_t)r * RS2 + part * 16;
            *(uint4*)(sm + AT_Q + off) = *(const uint4*)((const char*)g_q16 + gs);
        }
        const size_t kbase = ((size_t)b * T_) * H_;
        const uint32_t stg = smb + AT_ST0;
        for (int idx = tid; idx < 512; idx += 256) {
            int r = idx >> 3, part = idx & 7;
            size_t gs = (kbase + (size_t)r * H_ + part * 8) * 2;
            uint32_t off = (uint32_t)r * RS2 + part * 16;
            cp_async16(stg + AT_K + off, (const char*)g_k16 + gs);
            cp_async16(stg + AT_V + off, (const char*)g_v16 + gs);
        }
        CP_COMMIT();
    }
    __syncthreads();

    // preload Q A-frags
    uint32_t qa[4][4];
    {
        uint32_t a_row_off = (uint32_t)(w * 16 + (lane & 15)) * RS2
                           + (uint32_t)(lane >> 4) * 16;
#pragma unroll
        for (int ks = 0; ks < 4; ks++)
            ldsm_x4(qa[ks][0], qa[ks][1], qa[ks][2], qa[ks][3],
                    smb + AT_Q + a_row_off + ks * 32);
    }

    float o[8][4];
#pragma unroll
    for (int nt = 0; nt < 8; nt++)
#pragma unroll
        for (int i = 0; i < 4; i++) o[nt][i] = 0.f;
    float m0r = -INFINITY, m1r = -INFINITY;
    float l0r = 0.f, l1r = 0.f;

    const uint32_t kb_off = (uint32_t)(((lane >> 4) & 1) * 8 + (lane & 7)) * RS2
                          + (uint32_t)((lane >> 3) & 1) * 16;
    const uint32_t vb_off = (uint32_t)(((lane >> 3) & 1) * 8 + (lane & 7)) * RS2
                          + (uint32_t)((lane >> 4) & 1) * 16;

    for (int kt = 0; kt < nkt; kt++) {
        if (kt + 1 < nkt) {
            const size_t kbase = ((size_t)b * T_ + (kt + 1) * 64) * H_;
            const uint32_t stg = smb + AT_ST0 + ((kt + 1) & 1) * AT_STAGE;
            for (int idx = tid; idx < 512; idx += 256) {
                int r = idx >> 3, part = idx & 7;
                size_t gs = (kbase + (size_t)r * H_ + part * 8) * 2;
                uint32_t off = (uint32_t)r * RS2 + part * 16;
                cp_async16(stg + AT_K + off, (const char*)g_k16 + gs);
                cp_async16(stg + AT_V + off, (const char*)g_v16 + gs);
            }
            CP_COMMIT();
            CP_WAIT(1);
        } else {
            CP_WAIT(0);
        }
        __syncthreads();

        const int kcol0 = kt * 64;
        if (kcol0 <= rowbase + 15) {
            const uint32_t stg = smb + AT_ST0 + (kt & 1) * AT_STAGE;

            // S = Q K^T
            float s[8][4];
#pragma unroll
            for (int nt = 0; nt < 8; nt++)
#pragma unroll
                for (int i = 0; i < 4; i++) s[nt][i] = 0.f;

#pragma unroll
            for (int ks = 0; ks < 4; ks++) {
                uint32_t bfr[8][2];
#pragma unroll
                for (int np = 0; np < 4; np++) {
                    uint32_t off = kb_off + (uint32_t)np * 16 * RS2 + (uint32_t)ks * 32;
                    ldsm_x4(bfr[np*2][0], bfr[np*2][1], bfr[np*2+1][0], bfr[np*2+1][1],
                            stg + AT_K + off);
                }
#pragma unroll
                for (int nt = 0; nt < 8; nt++)
                    mma_f16(s[nt], qa[ks], bfr[nt]);
            }

            // causal mask (diagonal region)
            if (kcol0 + 63 > rowbase) {
                const int r0g = rowbase + g;
#pragma unroll
                for (int nt = 0; nt < 8; nt++) {
                    int cg = kcol0 + nt * 8 + tg * 2;
                    if (cg > r0g)         s[nt][0] = -1e30f;
                    if (cg + 1 > r0g)     s[nt][1] = -1e30f;
                    if (cg > r0g + 8)     s[nt][2] = -1e30f;
                    if (cg + 1 > r0g + 8) s[nt][3] = -1e30f;
                }
            }

            // online softmax
            float mt0 = -INFINITY, mt1 = -INFINITY;
#pragma unroll
            for (int nt = 0; nt < 8; nt++) {
                mt0 = fmaxf(mt0, fmaxf(s[nt][0], s[nt][1]));
                mt1 = fmaxf(mt1, fmaxf(s[nt][2], s[nt][3]));
            }
            mt0 = fmaxf(mt0, __shfl_xor_sync(0xffffffff, mt0, 1));
            mt0 = fmaxf(mt0, __shfl_xor_sync(0xffffffff, mt0, 2));
            mt1 = fmaxf(mt1, __shfl_xor_sync(0xffffffff, mt1, 1));
            mt1 = fmaxf(mt1, __shfl_xor_sync(0xffffffff, mt1, 2));

            float mn0 = fmaxf(m0r, mt0);
            float mn1 = fmaxf(m1r, mt1);
            float cr0 = __expf(m0r - mn0);
            float cr1 = __expf(m1r - mn1);
            m0r = mn0; m1r = mn1;

            float ls0 = 0.f, ls1 = 0.f;
#pragma unroll
            for (int nt = 0; nt < 8; nt++) {
                s[nt][0] = __expf(s[nt][0] - mn0);
                s[nt][1] = __expf(s[nt][1] - mn0);
                s[nt][2] = __expf(s[nt][2] - mn1);
                s[nt][3] = __expf(s[nt][3] - mn1);
                ls0 += s[nt][0] + s[nt][1];
                ls1 += s[nt][2] + s[nt][3];
            }
            l0r = l0r * cr0 + ls0;
            l1r = l1r * cr1 + ls1;

#pragma unroll
            for (int nt = 0; nt < 8; nt++) {
                o[nt][0] *= cr0; o[nt][1] *= cr0;
                o[nt][2] *= cr1; o[nt][3] *= cr1;
            }

            // repack P -> fp16 A-frags
            uint32_t pa[4][4];
#pragma unroll
            for (int j = 0; j < 4; j++) {
                pa[j][0] = pack_h2(s[2*j][0],   s[2*j][1]);
                pa[j][1] = pack_h2(s[2*j][2],   s[2*j][3]);
                pa[j][2] = pack_h2(s[2*j+1][0], s[2*j+1][1]);
                pa[j][3] = pack_h2(s[2*j+1][2], s[2*j+1][3]);
            }

            // O += P V
#pragma unroll
            for (int ks = 0; ks < 4; ks++) {
                uint32_t vb[8][2];
#pragma unroll
                for (int nt2 = 0; nt2 < 4; nt2++) {
                    uint32_t off = vb_off + (uint32_t)(ks * 16) * RS2 + (uint32_t)nt2 * 32;
                    ldsm_x4_t(vb[nt2*2][0], vb[nt2*2][1], vb[nt2*2+1][0], vb[nt2*2+1][1],
                              stg + AT_V + off);
                }
#pragma unroll
                for (int nt = 0; nt < 8; nt++)
                    mma_f16(o[nt], pa[ks], vb[nt]);
            }
        }
        __syncthreads();
    }

    // finalize
    l0r += __shfl_xor_sync(0xffffffff, l0r, 1);
    l0r += __shfl_xor_sync(0xffffffff, l0r, 2);
    l1r += __shfl_xor_sync(0xffffffff, l1r, 1);
    l1r += __shfl_xor_sync(0xffffffff, l1r, 2);
    float inv0 = 1.f / l0r;
    float inv1 = 1.f / l1r;

    const int q0 = rowbase + g;
#pragma unroll
    for (int nt = 0; nt < 8; nt++) {
        int h = nt * 8 + tg * 2;
        *(float2*)&out[((size_t)b * T_ + q0) * H_ + h] =
            make_float2(o[nt][0] * inv0, o[nt][1] * inv0);
        *(float2*)&out[((size_t)b * T_ + q0 + 8) * H_ + h] =
            make_float2(o[nt][2] * inv1, o[nt][3] * inv1);
    }
}

// ---------------------------------------------------------------------------
extern "C" void kernel_launch(void* const* d_in, const int* in_sizes, int n_in,
                              void* d_out, int out_size)
{
    const float* x  = (const float*)d_in[0];
    const float* Wk = (const float*)d_in[1];
    const float* Wq = (const float*)d_in[2];
    const float* Wv = (const float*)d_in[3];
    float* out = (float*)d_out;

    cudaFuncSetAttribute(qkv_gemm_pipe,
                         cudaFuncAttributeMaxDynamicSharedMemorySize, QK_SMEM);
    cudaFuncSetAttribute(attn_mma,
                         cudaFuncAttributeMaxDynamicSharedMemorySize, A_SMEM);

    dim3 gw(C_ / 32, H_ / 32, 3);
    wconv<<<gw, 256>>>(Wq, Wk, Wv);
    qkv_gemm_pipe<<<BT_ / 64, 256, QK_SMEM>>>(x);

    dim3 g2(B_, T_ / 128);
    attn_mma<<<g2, 256, A_SMEM>>>(out);
}

// round 15
// speedup vs baseline: 1.1733x; 1.0067x over previous
#include <cuda_runtime.h>
#include <cuda_fp16.h>
#include <math.h>
#include <stdint.h>

#define B_   256
#define T_   256
#define C_   512
#define H_   64
#define BT_  (B_ * T_)

// projected q (pre-scaled by C^-0.5), k, v as fp16
__device__ __half g_q16[BT_ * H_];
__device__ __half g_k16[BT_ * H_];
__device__ __half g_v16[BT_ * H_];

// W in B-operand layout [w][n=64][k=512], fp16
__device__ __half g_w16[3 * H_ * C_];

// ---------------------------------------------------------------------------
// helpers
// ---------------------------------------------------------------------------
__device__ __forceinline__ uint32_t smem_u32(const void* p) {
    uint32_t a;
    asm("{ .reg .u64 t; cvta.to.shared.u64 t, %1; cvt.u32.u64 %0, t; }"
        : "=r"(a) : "l"(p));
    return a;
}

__device__ __forceinline__ void ldsm_x4(uint32_t& r0, uint32_t& r1,
                                        uint32_t& r2, uint32_t& r3,
                                        uint32_t addr) {
    asm volatile("ldmatrix.sync.aligned.m8n8.x4.shared.b16 {%0,%1,%2,%3}, [%4];"
                 : "=r"(r0), "=r"(r1), "=r"(r2), "=r"(r3) : "r"(addr));
}

__device__ __forceinline__ void ldsm_x4_t(uint32_t& r0, uint32_t& r1,
                                          uint32_t& r2, uint32_t& r3,
                                          uint32_t addr) {
    asm volatile("ldmatrix.sync.aligned.m8n8.x4.trans.shared.b16 {%0,%1,%2,%3}, [%4];"
                 : "=r"(r0), "=r"(r1), "=r"(r2), "=r"(r3) : "r"(addr));
}

__device__ __forceinline__ void mma_f16(float* c, const uint32_t* a,
                                        const uint32_t* b) {
    asm volatile(
        "mma.sync.aligned.m16n8k16.row.col.f32.f16.f16.f32 "
        "{%0,%1,%2,%3}, {%4,%5,%6,%7}, {%8,%9}, {%0,%1,%2,%3};"
        : "+f"(c[0]), "+f"(c[1]), "+f"(c[2]), "+f"(c[3])
        : "r"(a[0]), "r"(a[1]), "r"(a[2]), "r"(a[3]),
          "r"(b[0]), "r"(b[1]));
}

__device__ __forceinline__ uint32_t pack_h2(float lo, float hi) {
    __half2 t = __floats2half2_rn(lo, hi);
    return *(uint32_t*)&t;
}

__device__ __forceinline__ void cp_async16(uint32_t smem_addr, const void* gptr) {
    asm volatile("cp.async.cg.shared.global [%0], [%1], 16;"
                 :: "r"(smem_addr), "l"(gptr));
}
// L1-allocating variant: co-resident CTAs on the same SM stream identical W
// bytes, so the trailing CTA hits L1 and W's LTS traffic is halved.
__device__ __forceinline__ void cp_async16_ca(uint32_t smem_addr, const void* gptr) {
    asm volatile("cp.async.ca.shared.global [%0], [%1], 16;"
                 :: "r"(smem_addr), "l"(gptr));
}
#define CP_COMMIT()  asm volatile("cp.async.commit_group;")
#define CP_WAIT(N)   asm volatile("cp.async.wait_group %0;" :: "n"(N))

#define RS2 144   // smem row stride in bytes (72 halves)

// ---------------------------------------------------------------------------
// Kernel 0: W -> fp16 in [w][h][c] layout (smem tile transpose, coalesced)
// ---------------------------------------------------------------------------
__global__ void wconv(const float* __restrict__ Wq,
                      const float* __restrict__ Wk,
                      const float* __restrict__ Wv)
{
    __shared__ float tile[32][33];
    const int w  = blockIdx.z;
    const int c0 = blockIdx.x * 32;
    const int h0 = blockIdx.y * 32;
    const float* W = (w == 0) ? Wq : (w == 1) ? Wk : Wv;

    const int tx = threadIdx.x & 31;
    const int ty = threadIdx.x >> 5;

#pragma unroll
    for (int i = 0; i < 4; i++) {
        int r = ty + i * 8;
        tile[r][tx] = W[(size_t)(c0 + r) * H_ + h0 + tx];
    }
    __syncthreads();
#pragma unroll
    for (int i = 0; i < 4; i++) {
        int hh = ty + i * 8;
        g_w16[((size_t)w * H_ + h0 + hh) * C_ + c0 + tx] =
            __float2half(tile[tx][hh]);
    }
}

// ---------------------------------------------------------------------------
// Kernel 1: pipelined fused QKV projection, single-term fp16 (R8 config —
// measured local optimum: 256 threads, 2 CTAs/SM, 32x48 warp tiles,
// B double-buffered cp.async (.ca for W reuse), x register-prefetched one
// chunk ahead).
// smem: A 0 (9216), B0 9216 (27648), B1 36864 (27648); total 64512
// ---------------------------------------------------------------------------
#define QK_A  0
#define QK_B0 9216
#define QK_B1 36864
#define QK_SMEM 64512

__global__ __launch_bounds__(256, 2) void qkv_gemm_pipe(
    const float* __restrict__ x)
{
    extern __shared__ char sm[];
    const uint32_t smb = smem_u32(sm);

    const int tid  = threadIdx.x;
    const int wid  = tid >> 5;
    const int lane = tid & 31;
    const int row0 = blockIdx.x * 64;

    const int wm = wid & 1;
    const int wn = wid >> 1;          // 0..3
    const int m0 = wm * 32;
    const int n0 = wn * 48;

    float c[2][6][4];
#pragma unroll
    for (int mt = 0; mt < 2; mt++)
#pragma unroll
        for (int nt = 0; nt < 6; nt++)
#pragma unroll
            for (int i = 0; i < 4; i++) c[mt][nt][i] = 0.f;

    const uint32_t a_row_off = (uint32_t)(m0 + (lane & 15)) * RS2
                             + (uint32_t)(lane >> 4) * 16;
    const uint32_t b_row_off = (uint32_t)(n0 + ((lane >> 4) & 1) * 8 + (lane & 7)) * RS2
                             + (uint32_t)((lane >> 3) & 1) * 16;

    const float4* x4 = (const float4*)x;

    // prologue: B chunk 0 via cp.async (.ca), x chunk 0 into regs
    {
#pragma unroll
        for (int it = 0; it < 6; it++) {
            int idx = tid + it * 256;          // 0..1535
            int n = idx >> 3, part = idx & 7;
            size_t gs = ((size_t)n * C_) * 2 + (size_t)part * 16;
            uint32_t off = (uint32_t)n * RS2 + (uint32_t)part * 16;
            cp_async16_ca(smb + QK_B0 + off, (const char*)g_w16 + gs);
        }
        CP_COMMIT();
    }

    float4 xv[4];
#pragma unroll
    for (int it = 0; it < 4; it++) {
        int idx = tid + it * 256;
        int r = idx >> 4, c4 = idx & 15;
        xv[it] = x4[(size_t)(row0 + r) * 128 + c4];
    }

    for (int ch = 0; ch < 8; ch++) {
        // convert x regs -> A fp16 smem
#pragma unroll
        for (int it = 0; it < 4; it++) {
            int idx = tid + it * 256;
            int r = idx >> 4, c4 = idx & 15;
            float4 v = xv[it];
            uint32_t off = (uint32_t)r * RS2 + (uint32_t)c4 * 8;
            *(uint2*)(sm + QK_A + off) =
                make_uint2(pack_h2(v.x, v.y), pack_h2(v.z, v.w));
        }

        // prefetch chunk ch+1
        if (ch < 7) {
            const int c1 = (ch + 1) * 64;
#pragma unroll
            for (int it = 0; it < 4; it++) {
                int idx = tid + it * 256;
                int r = idx >> 4, c4 = idx & 15;
                xv[it] = x4[(size_t)(row0 + r) * 128 + (c1 >> 2) + c4];
            }
            const uint32_t bb = ((ch + 1) & 1) ? QK_B1 : QK_B0;
#pragma unroll
            for (int it = 0; it < 6; it++) {
                int idx = tid + it * 256;
                int n = idx >> 3, part = idx & 7;
                size_t gs = ((size_t)n * C_ + c1) * 2 + (size_t)part * 16;
                uint32_t off = (uint32_t)n * RS2 + (uint32_t)part * 16;
                cp_async16_ca(smb + bb + off, (const char*)g_w16 + gs);
            }
            CP_COMMIT();
            CP_WAIT(1);
        } else {
            CP_WAIT(0);
        }
        __syncthreads();

        const uint32_t bbuf = (ch & 1) ? QK_B1 : QK_B0;
#pragma unroll
        for (int ks = 0; ks < 4; ks++) {
            uint32_t a[2][4];
#pragma unroll
            for (int mt = 0; mt < 2; mt++) {
                uint32_t off = a_row_off + (uint32_t)mt * 16 * RS2 + (uint32_t)ks * 32;
                ldsm_x4(a[mt][0], a[mt][1], a[mt][2], a[mt][3], smb + QK_A + off);
            }
            uint32_t bfr[6][2];
#pragma unroll
            for (int np = 0; np < 3; np++) {
                uint32_t off = b_row_off + (uint32_t)np * 16 * RS2 + (uint32_t)ks * 32;
                ldsm_x4(bfr[np*2][0], bfr[np*2][1], bfr[np*2+1][0], bfr[np*2+1][1],
                        smb + bbuf + off);
            }
#pragma unroll
            for (int mt = 0; mt < 2; mt++)
#pragma unroll
                for (int nt = 0; nt < 6; nt++)
                    mma_f16(c[mt][nt], a[mt], bfr[nt]);
        }
        __syncthreads();
    }

    // epilogue: fp16 writes; q pre-scaled by C^-0.5
    const float SCALE = 0.04419417382415922f;
    const int g  = lane >> 2;
    const int tg = lane & 3;
#pragma unroll
    for (int nt = 0; nt < 6; nt++) {
        int col0 = n0 + nt * 8;
        int w = col0 >> 6;
        int h = (col0 & 63) + tg * 2;
        float mul = (w == 0) ? SCALE : 1.0f;
        __half* op = (w == 0) ? g_q16 : (w == 1) ? g_k16 : g_v16;
#pragma unroll
        for (int mt = 0; mt < 2; mt++)
#pragma unroll
            for (int rr = 0; rr < 2; rr++) {
                int row = row0 + m0 + mt * 16 + g + rr * 8;
                size_t o = (size_t)row * H_ + h;
                *(uint32_t*)(op + o) = pack_h2(c[mt][nt][rr * 2 + 0] * mul,
                                               c[mt][nt][rr * 2 + 1] * mul);
            }
    }
}

// ---------------------------------------------------------------------------
// Kernel 2: fp16 tensor-core causal flash attention (R8 config — measured
// optimum: Q-tile 128, 256 threads, double-buffered K/V cp.async stages,
// per-warp causal skip, 2 CTAs/SM).
// smem: Q 0 (18432), stage0 @18432 (K 9216, V 9216), stage1 @36864. 55296 B.
// ---------------------------------------------------------------------------
#define AT_Q  0
#define AT_ST0 18432
#define AT_STAGE 18432
#define AT_K 0
#define AT_V 9216
#define A_SMEM 55296

__global__ __launch_bounds__(256, 2) void attn_mma(float* __restrict__ out)
{
    extern __shared__ char sm[];
    const uint32_t smb = smem_u32(sm);

    const int b    = blockIdx.x;
    const int qt   = 1 - blockIdx.y;           // heavy tile first
    const int tid  = threadIdx.x;
    const int w    = tid >> 5;
    const int lane = tid & 31;
    const int g    = lane >> 2;
    const int tg   = lane & 3;

    const int rowbase = qt * 128 + w * 16;
    const int nkt = qt * 2 + 2;

    // Q tile (128 rows) + prologue K/V stage 0
    {
        const size_t base = ((size_t)b * T_ + qt * 128) * H_;   // halves
        for (int idx = tid; idx < 1024; idx += 256) {
            int r = idx >> 3, part = idx & 7;
            size_t gs = (base + (size_t)r * H_ + part * 8) * 2;
            uint32_t off = (uint32_t)r * RS2 + part * 16;
            *(uint4*)(sm + AT_Q + off) = *(const uint4*)((const char*)g_q16 + gs);
        }
        const size_t kbase = ((size_t)b * T_) * H_;
        const uint32_t stg = smb + AT_ST0;
        for (int idx = tid; idx < 512; idx += 256) {
            int r = idx >> 3, part = idx & 7;
            size_t gs = (kbase + (size_t)r * H_ + part * 8) * 2;
            uint32_t off = (uint32_t)r * RS2 + part * 16;
            cp_async16(stg + AT_K + off, (const char*)g_k16 + gs);
            cp_async16(stg + AT_V + off, (const char*)g_v16 + gs);
        }
        CP_COMMIT();
    }
    __syncthreads();

    // preload Q A-frags
    uint32_t qa[4][4];
    {
        uint32_t a_row_off = (uint32_t)(w * 16 + (lane & 15)) * RS2
                           + (uint32_t)(lane >> 4) * 16;
#pragma unroll
        for (int ks = 0; ks < 4; ks++)
            ldsm_x4(qa[ks][0], qa[ks][1], qa[ks][2], qa[ks][3],
                    smb + AT_Q + a_row_off + ks * 32);
    }

    float o[8][4];
#pragma unroll
    for (int nt = 0; nt < 8; nt++)
#pragma unroll
        for (int i = 0; i < 4; i++) o[nt][i] = 0.f;
    float m0r = -INFINITY, m1r = -INFINITY;
    float l0r = 0.f, l1r = 0.f;

    const uint32_t kb_off = (uint32_t)(((lane >> 4) & 1) * 8 + (lane & 7)) * RS2
                          + (uint32_t)((lane >> 3) & 1) * 16;
    const uint32_t vb_off = (uint32_t)(((lane >> 3) & 1) * 8 + (lane & 7)) * RS2
                          + (uint32_t)((lane >> 4) & 1) * 16;

    for (int kt = 0; kt < nkt; kt++) {
        if (kt + 1 < nkt) {
            const size_t kbase = ((size_t)b * T_ + (kt + 1) * 64) * H_;
            const uint32_t stg = smb + AT_ST0 + ((kt + 1) & 1) * AT_STAGE;
            for (int idx = tid; idx < 512; idx += 256) {
                int r = idx >> 3, part = idx & 7;
                size_t gs = (kbase + (size_t)r * H_ + part * 8) * 2;
                uint32_t off = (uint32_t)r * RS2 + part * 16;
                cp_async16(stg + AT_K + off, (const char*)g_k16 + gs);
                cp_async16(stg + AT_V + off, (const char*)g_v16 + gs);
            }
            CP_COMMIT();
            CP_WAIT(1);
        } else {
            CP_WAIT(0);
        }
        __syncthreads();

        const int kcol0 = kt * 64;
        if (kcol0 <= rowbase + 15) {
            const uint32_t stg = smb + AT_ST0 + (kt & 1) * AT_STAGE;

            // S = Q K^T
            float s[8][4];
#pragma unroll
            for (int nt = 0; nt < 8; nt++)
#pragma unroll
                for (int i = 0; i < 4; i++) s[nt][i] = 0.f;

#pragma unroll
            for (int ks = 0; ks < 4; ks++) {
                uint32_t bfr[8][2];
#pragma unroll
                for (int np = 0; np < 4; np++) {
                    uint32_t off = kb_off + (uint32_t)np * 16 * RS2 + (uint32_t)ks * 32;
                    ldsm_x4(bfr[np*2][0], bfr[np*2][1], bfr[np*2+1][0], bfr[np*2+1][1],
                            stg + AT_K + off);
                }
#pragma unroll
                for (int nt = 0; nt < 8; nt++)
                    mma_f16(s[nt], qa[ks], bfr[nt]);
            }

            // causal mask (diagonal region)
            if (kcol0 + 63 > rowbase) {
                const int r0g = rowbase + g;
#pragma unroll
                for (int nt = 0; nt < 8; nt++) {
                    int cg = kcol0 + nt * 8 + tg * 2;
                    if (cg > r0g)         s[nt][0] = -1e30f;
                    if (cg + 1 > r0g)     s[nt][1] = -1e30f;
                    if (cg > r0g + 8)     s[nt][2] = -1e30f;
                    if (cg + 1 > r0g + 8) s[nt][3] = -1e30f;
                }
            }

            // online softmax
            float mt0 = -INFINITY, mt1 = -INFINITY;
#pragma unroll
            for (int nt = 0; nt < 8; nt++) {
                mt0 = fmaxf(mt0, fmaxf(s[nt][0], s[nt][1]));
                mt1 = fmaxf(mt1, fmaxf(s[nt][2], s[nt][3]));
            }
            mt0 = fmaxf(mt0, __shfl_xor_sync(0xffffffff, mt0, 1));
            mt0 = fmaxf(mt0, __shfl_xor_sync(0xffffffff, mt0, 2));
            mt1 = fmaxf(mt1, __shfl_xor_sync(0xffffffff, mt1, 1));
            mt1 = fmaxf(mt1, __shfl_xor_sync(0xffffffff, mt1, 2));

            float mn0 = fmaxf(m0r, mt0);
            float mn1 = fmaxf(m1r, mt1);
            float cr0 = __expf(m0r - mn0);
            float cr1 = __expf(m1r - mn1);
            m0r = mn0; m1r = mn1;

            float ls0 = 0.f, ls1 = 0.f;
#pragma unroll
            for (int nt = 0; nt < 8; nt++) {
                s[nt][0] = __expf(s[nt][0] - mn0);
                s[nt][1] = __expf(s[nt][1] - mn0);
                s[nt][2] = __expf(s[nt][2] - mn1);
                s[nt][3] = __expf(s[nt][3] - mn1);
                ls0 += s[nt][0] + s[nt][1];
                ls1 += s[nt][2] + s[nt][3];
            }
            l0r = l0r * cr0 + ls0;
            l1r = l1r * cr1 + ls1;

#pragma unroll
            for (int nt = 0; nt < 8; nt++) {
                o[nt][0] *= cr0; o[nt][1] *= cr0;
                o[nt][2] *= cr1; o[nt][3] *= cr1;
            }

            // repack P -> fp16 A-frags
            uint32_t pa[4][4];
#pragma unroll
            for (int j = 0; j < 4; j++) {
                pa[j][0] = pack_h2(s[2*j][0],   s[2*j][1]);
                pa[j][1] = pack_h2(s[2*j][2],   s[2*j][3]);
                pa[j][2] = pack_h2(s[2*j+1][0], s[2*j+1][1]);
                pa[j][3] = pack_h2(s[2*j+1][2], s[2*j+1][3]);
            }

            // O += P V
#pragma unroll
            for (int ks = 0; ks < 4; ks++) {
                uint32_t vb[8][2];
#pragma unroll
                for (int nt2 = 0; nt2 < 4; nt2++) {
                    uint32_t off = vb_off + (uint32_t)(ks * 16) * RS2 + (uint32_t)nt2 * 32;
                    ldsm_x4_t(vb[nt2*2][0], vb[nt2*2][1], vb[nt2*2+1][0], vb[nt2*2+1][1],
                              stg + AT_V + off);
                }
#pragma unroll
                for (int nt = 0; nt < 8; nt++)
                    mma_f16(o[nt], pa[ks], vb[nt]);
            }
        }
        __syncthreads();
    }

    // finalize
    l0r += __shfl_xor_sync(0xffffffff, l0r, 1);
    l0r += __shfl_xor_sync(0xffffffff, l0r, 2);
    l1r += __shfl_xor_sync(0xffffffff, l1r, 1);
    l1r += __shfl_xor_sync(0xffffffff, l1r, 2);
    float inv0 = 1.f / l0r;
    float inv1 = 1.f / l1r;

    const int q0 = rowbase + g;
#pragma unroll
    for (int nt = 0; nt < 8; nt++) {
        int h = nt * 8 + tg * 2;
        *(float2*)&out[((size_t)b * T_ + q0) * H_ + h] =
            make_float2(o[nt][0] * inv0, o[nt][1] * inv0);
        *(float2*)&out[((size_t)b * T_ + q0 + 8) * H_ + h] =
            make_float2(o[nt][2] * inv1, o[nt][3] * inv1);
    }
}

// ---------------------------------------------------------------------------
extern "C" void kernel_launch(void* const* d_in, const int* in_sizes, int n_in,
                              void* d_out, int out_size)
{
    const float* x  = (const float*)d_in[0];
    const float* Wk = (const float*)d_in[1];
    const float* Wq = (const float*)d_in[2];
    const float* Wv = (const float*)d_in[3];
    float* out = (float*)d_out;

    cudaFuncSetAttribute(qkv_gemm_pipe,
                         cudaFuncAttributeMaxDynamicSharedMemorySize, QK_SMEM);
    cudaFuncSetAttribute(attn_mma,
                         cudaFuncAttributeMaxDynamicSharedMemorySize, A_SMEM);

    dim3 gw(C_ / 32, H_ / 32, 3);
    wconv<<<gw, 256>>>(Wq, Wk, Wv);
    qkv_gemm_pipe<<<BT_ / 64, 256, QK_SMEM>>>(x);

    dim3 g2(B_, T_ / 128);
    attn_mma<<<g2, 256, A_SMEM>>>(out);
}